// round 6
// baseline (speedup 1.0000x reference)
#include <cuda_runtime.h>
#include <math.h>

// ---- problem constants (shapes fixed by the dataset) ----
#define NROWS      196608LL   // 4*3*128*128 z-rows of 128 floats
#define ROWS_PT    64         // rows per block tile
#define NBLOCKS    3072       // NROWS / ROWS_PT
// padded smem layout: quarter stride 36 words, row stride 144 words
#define QSTRIDE    36
#define RSTRIDE    144

// Per-block partials: .x = sum(x^2), .y = sum over rows of (s0^2 + s1^2)
__device__ double2 g_part[NBLOCKS];
__device__ unsigned int g_ticket;   // zero-init; last block resets -> graph-replay safe

// Stage a 64x128 float tile through padded smem so the z-row reduction becomes
// thread-local (zero per-element shuffles):
//   load:  8x LDG.128/thread coalesced -> STS.128 into padded layout
//          word(r, f4) = r*144 + (f4>>3)*36 + (f4&7)*4   (conflict-free)
//   compute: thread (r = tid>>2, q = tid&3) owns z in [32q, 32q+32):
//          8x LDS.128, accumulate e, p0 = sum(x), p1 = sum((-1)^z x) in regs
//          (float4 starts at even z -> component signs +,-,+,- always)
//   combine: 4 lanes/row -> 4 shfl_xor per 8 rows; lane q==0 adds s0^2+s1^2.
// Final loss = c0 + c1*E + c2*S, host-precomputed (see kernel_launch).
__global__ void __launch_bounds__(256) spectral_kernel(const float4* __restrict__ x4,
                                                       float* __restrict__ out,
                                                       double c0, double c1, double c2) {
    __shared__ float tile[ROWS_PT * RSTRIDE];   // 36 KB
    const int tid = threadIdx.x;

    // ---- load: 2048 float4 per tile, 8 per thread, all independent ----
    const float4* __restrict__ src = x4 + (long long)blockIdx.x * (ROWS_PT * 32) + tid;
    #pragma unroll
    for (int k = 0; k < 8; k++) {
        const float4 v = src[k * 256];
        const int m = tid + k * 256;          // linear float4 index in tile
        const int r = m >> 5;                 // row 0..63
        const int f = m & 31;                 // float4 within row
        const int w = r * RSTRIDE + (f >> 3) * QSTRIDE + (f & 7) * 4;
        *reinterpret_cast<float4*>(tile + w) = v;
    }
    __syncthreads();

    // ---- compute: thread-local quarter-row reduction ----
    const int r = tid >> 2;
    const int q = tid & 3;
    const float* __restrict__ rp = tile + r * RSTRIDE + q * QSTRIDE;

    float e = 0.0f, p0 = 0.0f, p1 = 0.0f;
    #pragma unroll
    for (int j = 0; j < 8; j++) {
        const float4 w = *reinterpret_cast<const float4*>(rp + 4 * j);
        e  += w.x * w.x + w.y * w.y + w.z * w.z + w.w * w.w;
        p0 += (w.x + w.y) + (w.z + w.w);
        p1 += (w.x - w.y) + (w.z - w.w);
    }

    // combine the 4 quarter-lanes of each row (lanes 4r..4r+3)
    p0 += __shfl_xor_sync(0xffffffffu, p0, 1);
    p1 += __shfl_xor_sync(0xffffffffu, p1, 1);
    p0 += __shfl_xor_sync(0xffffffffu, p0, 2);
    p1 += __shfl_xor_sync(0xffffffffu, p1, 2);
    float ss = (q == 0) ? (p0 * p0 + p1 * p1) : 0.0f;

    // warp-wide reduce of e and ss
    #pragma unroll
    for (int o = 16; o > 0; o >>= 1) {
        e  += __shfl_xor_sync(0xffffffffu, e,  o);
        ss += __shfl_xor_sync(0xffffffffu, ss, o);
    }

    __shared__ float sh_e[8];
    __shared__ float sh_s[8];
    const int lane = tid & 31, wib = tid >> 5;
    if (lane == 0) { sh_e[wib] = e; sh_s[wib] = ss; }
    __syncthreads();

    __shared__ bool is_last;
    if (tid == 0) {
        double te = 0.0, ts = 0.0;
        #pragma unroll
        for (int i = 0; i < 8; i++) { te += (double)sh_e[i]; ts += (double)sh_s[i]; }
        g_part[blockIdx.x] = make_double2(te, ts);
        __threadfence();
        unsigned int t = atomicAdd(&g_ticket, 1u);
        is_last = (t == NBLOCKS - 1);
    }
    __syncthreads();

    if (!is_last) return;

    // ---- last block: reduce all partials (hot in L2) and finalize ----
    double te = 0.0, ts = 0.0;
    #pragma unroll
    for (int i = 0; i < NBLOCKS / 256; i++) {
        const double2 p = g_part[tid + i * 256];
        te += p.x; ts += p.y;
    }
    #pragma unroll
    for (int o = 16; o > 0; o >>= 1) {
        te += __shfl_xor_sync(0xffffffffu, te, o);
        ts += __shfl_xor_sync(0xffffffffu, ts, o);
    }
    __shared__ double fh_e[8];
    __shared__ double fh_s[8];
    if (lane == 0) { fh_e[wib] = te; fh_s[wib] = ts; }
    __syncthreads();

    if (tid == 0) {
        double E = 0.0, S = 0.0;
        #pragma unroll
        for (int i = 0; i < 8; i++) { E += fh_e[i]; S += fh_s[i]; }
        out[0] = (float)(c0 + c1 * E + c2 * S);
        g_ticket = 0;   // reset for next graph replay
    }
}

extern "C" void kernel_launch(void* const* d_in, const int* in_sizes, int n_in,
                              void* d_out, int out_size) {
    const float4* x4 = (const float4*)d_in[0];
    float* out = (float*)d_out;

    // ---- host-side constant folding ----
    // Derivation: k_mag uses NORMALIZED fft freqs (<= sqrt(3)/2); k_bins =
    // linspace(0,32,32) (k_max = min(128,128,65)//2 = 32) has spacing 32/31 >
    // sqrt(3)/2 => every point lands in bin 1:
    //   spectrum[1] = E_half/(128*128*65*4), all other bins zero.
    // E_half via Parseval: 0.5*(128^3*sum(x^2) + 128^2*sum(s0^2+s1^2)),
    // s0/s1 = plain/alternating z-sums (kz=0 / kz=Nyquist planes = 2D FFTs
    // of those sums). decay loss (spectrum[9:]==0) is the data-independent
    // constant mean_{k=9..31}((k^{-5/3}/(9^{-5/3}+1e-8))^2); cascade =
    // spectrum[1]/31.
    const double p = -5.0 / 3.0;
    const double denom = pow(9.0, p) + 1e-8;
    double acc = 0.0;
    for (int k = 9; k < 32; k++) {
        double en = pow((double)k, p) / denom;
        acc += en * en;
    }
    const double decay_loss = acc / 23.0;

    const double inv_npts = 1.0 / (128.0 * 128.0 * 65.0 * 4.0);
    const double c_casc   = 0.001 / 31.0;
    const double c0 = 0.01 * decay_loss;
    const double c1 = c_casc * 0.5 * 2097152.0 * inv_npts;   // * E = sum(x^2)
    const double c2 = c_casc * 0.5 * 16384.0   * inv_npts;   // * S = sum(s0^2+s1^2)

    spectral_kernel<<<NBLOCKS, 256>>>(x4, out, c0, c1, c2);
}

// round 7
// speedup vs baseline: 1.7047x; 1.7047x over previous
#include <cuda_runtime.h>
#include <math.h>
#include <stdint.h>

// ---- problem constants (shapes fixed by the dataset) ----
#define NROWS      196608LL   // 4*3*128*128 z-rows of 128 floats
#define TILE_ROWS  32         // rows per pipeline stage (16 KB)
#define TILES_PB   8          // tiles per block -> 256 rows per block
#define NBLOCKS    768        // NROWS / (TILE_ROWS * TILES_PB)
#define TILE_F4    (TILE_ROWS * 32)      // float4 per tile
#define TILE_BYTES (TILE_ROWS * 512)     // 16384

// Per-block partials: .x = sum(x^2), .y = sum over rows of (s0^2 + s1^2)
__device__ double2 g_part[NBLOCKS];
__device__ unsigned int g_ticket;   // zero-init; last block resets -> graph-replay safe

__device__ __forceinline__ uint32_t smem_u32(const void* p) {
    uint32_t a;
    asm("{ .reg .u64 t; cvta.to.shared.u64 t, %1; cvt.u32.u64 %0, t; }" : "=r"(a) : "l"(p));
    return a;
}

__device__ __forceinline__ void mbar_init(uint32_t mbar, uint32_t count) {
    asm volatile("mbarrier.init.shared.b64 [%0], %1;" :: "r"(mbar), "r"(count) : "memory");
}
__device__ __forceinline__ void mbar_expect_tx(uint32_t mbar, uint32_t bytes) {
    asm volatile("mbarrier.arrive.expect_tx.shared.b64 _, [%0], %1;" :: "r"(mbar), "r"(bytes) : "memory");
}
__device__ __forceinline__ void bulk_copy_g2s(uint32_t dst, const void* src, uint32_t bytes, uint32_t mbar) {
    asm volatile("cp.async.bulk.shared::cta.global.mbarrier::complete_tx::bytes [%0], [%1], %2, [%3];"
                 :: "r"(dst), "l"(src), "r"(bytes), "r"(mbar) : "memory");
}
__device__ __forceinline__ void mbar_wait_parity(uint32_t mbar, uint32_t parity) {
    asm volatile(
        "{\n\t"
        ".reg .pred P1;\n\t"
        "WAIT_LOOP_%=:\n\t"
        "mbarrier.try_wait.parity.shared.b64 P1, [%0], %1, 0x989680;\n\t"
        "@P1 bra.uni WAIT_DONE_%=;\n\t"
        "bra.uni WAIT_LOOP_%=;\n\t"
        "WAIT_DONE_%=:\n\t"
        "}"
        :: "r"(mbar), "r"(parity) : "memory");
}

// Pipeline: one elected thread streams 16KB tiles via cp.async.bulk (UBLKCP —
// bypasses the per-thread LDG path, runs at the LTS/HBM cap); 256 threads
// compute the previous tile from smem.
//
// Compute: thread (r = tid>>3, o = tid&7) owns row r's 16 floats [o*16, o*16+16)
// as 4 LDS.128, read in rotated order j_eff = (j + (o>>1)) & 3 so each 8-lane
// LDS phase hits 8 distinct 4-bank groups (conflict-free). z of a float4 starts
// even -> alternating signs are always +,-,+,-.
// Per-row combine over the 8 o-lanes: shfl_xor 1,2,4 on p0 and p1 (6 shuffles
// per row, amortized over 128 floats); lane o==0 accumulates s0^2+s1^2.
//
// Final loss = c0 + c1*E + c2*S (host-precomputed; see kernel_launch).
__global__ void __launch_bounds__(256) spectral_kernel(const float4* __restrict__ x4,
                                                       float* __restrict__ out,
                                                       double c0, double c1, double c2) {
    __shared__ alignas(1024) float4 buf[2][TILE_F4];     // 2 x 16 KB
    __shared__ alignas(8) uint64_t mbar_store[2];

    const int tid  = threadIdx.x;
    const int lane = tid & 31, wib = tid >> 5;
    const uint32_t mb0 = smem_u32(&mbar_store[0]);
    const uint32_t mb1 = smem_u32(&mbar_store[1]);

    const float4* __restrict__ src = x4 + (long long)blockIdx.x * (TILES_PB * TILE_F4);

    if (tid == 0) {
        mbar_init(mb0, 1);
        mbar_init(mb1, 1);
        asm volatile("fence.proxy.async.shared::cta;" ::: "memory");
    }
    __syncthreads();

    if (tid == 0) {
        mbar_expect_tx(mb0, TILE_BYTES);
        bulk_copy_g2s(smem_u32(&buf[0][0]), src,            TILE_BYTES, mb0);
        mbar_expect_tx(mb1, TILE_BYTES);
        bulk_copy_g2s(smem_u32(&buf[1][0]), src + TILE_F4,  TILE_BYTES, mb1);
    }

    const int r = tid >> 3;          // row within tile, 0..31
    const int o = tid & 7;           // eighth within row, 0..7
    const int rot = o >> 1;
    const float4* __restrict__ my0 = &buf[0][r * 32 + o * 4];
    const float4* __restrict__ my1 = &buf[1][r * 32 + o * 4];

    float e = 0.0f, ss = 0.0f;

    #pragma unroll
    for (int t = 0; t < TILES_PB; t++) {
        const int s = t & 1;
        const uint32_t mb = s ? mb1 : mb0;
        mbar_wait_parity(mb, (t >> 1) & 1);

        const float4* __restrict__ my = s ? my1 : my0;
        float p0 = 0.0f, p1 = 0.0f;
        #pragma unroll
        for (int j = 0; j < 4; j++) {
            const float4 w = my[(j + rot) & 3];
            e  += w.x * w.x + w.y * w.y + w.z * w.z + w.w * w.w;
            p0 += (w.x + w.y) + (w.z + w.w);
            p1 += (w.x - w.y) + (w.z - w.w);
        }
        // combine 8 o-lanes of this row
        p0 += __shfl_xor_sync(0xffffffffu, p0, 1);
        p1 += __shfl_xor_sync(0xffffffffu, p1, 1);
        p0 += __shfl_xor_sync(0xffffffffu, p0, 2);
        p1 += __shfl_xor_sync(0xffffffffu, p1, 2);
        p0 += __shfl_xor_sync(0xffffffffu, p0, 4);
        p1 += __shfl_xor_sync(0xffffffffu, p1, 4);
        if (o == 0) ss += p0 * p0 + p1 * p1;

        __syncthreads();             // all threads done reading stage s
        if (tid == 0 && t + 2 < TILES_PB) {
            mbar_expect_tx(mb, TILE_BYTES);
            bulk_copy_g2s(smem_u32(s ? &buf[1][0] : &buf[0][0]),
                          src + (long long)(t + 2) * TILE_F4, TILE_BYTES, mb);
        }
    }

    // warp-wide reduce of e and ss
    #pragma unroll
    for (int off = 16; off > 0; off >>= 1) {
        e  += __shfl_xor_sync(0xffffffffu, e,  off);
        ss += __shfl_xor_sync(0xffffffffu, ss, off);
    }

    __shared__ float sh_e[8];
    __shared__ float sh_s[8];
    if (lane == 0) { sh_e[wib] = e; sh_s[wib] = ss; }
    __syncthreads();

    __shared__ bool is_last;
    if (tid == 0) {
        double te = 0.0, ts = 0.0;
        #pragma unroll
        for (int i = 0; i < 8; i++) { te += (double)sh_e[i]; ts += (double)sh_s[i]; }
        g_part[blockIdx.x] = make_double2(te, ts);
        __threadfence();
        unsigned int tk = atomicAdd(&g_ticket, 1u);
        is_last = (tk == NBLOCKS - 1);
    }
    __syncthreads();

    if (!is_last) return;

    // ---- last block: reduce all partials (hot in L2) and finalize ----
    double te = 0.0, ts = 0.0;
    #pragma unroll
    for (int i = 0; i < NBLOCKS / 256; i++) {
        const double2 p = g_part[tid + i * 256];
        te += p.x; ts += p.y;
    }
    #pragma unroll
    for (int off = 16; off > 0; off >>= 1) {
        te += __shfl_xor_sync(0xffffffffu, te, off);
        ts += __shfl_xor_sync(0xffffffffu, ts, off);
    }
    __shared__ double fh_e[8];
    __shared__ double fh_s[8];
    if (lane == 0) { fh_e[wib] = te; fh_s[wib] = ts; }
    __syncthreads();

    if (tid == 0) {
        double E = 0.0, S = 0.0;
        #pragma unroll
        for (int i = 0; i < 8; i++) { E += fh_e[i]; S += fh_s[i]; }
        out[0] = (float)(c0 + c1 * E + c2 * S);
        g_ticket = 0;   // reset for next graph replay
    }
}

extern "C" void kernel_launch(void* const* d_in, const int* in_sizes, int n_in,
                              void* d_out, int out_size) {
    const float4* x4 = (const float4*)d_in[0];
    float* out = (float*)d_out;

    // ---- host-side constant folding ----
    // k_mag uses NORMALIZED fft freqs (<= sqrt(3)/2); k_bins = linspace(0,32,32)
    // (k_max = min(128,128,65)//2 = 32) has spacing 32/31 > sqrt(3)/2 => every
    // point lands in bin 1: spectrum[1] = E_half/(128*128*65*4), rest zero.
    // E_half via Parseval: 0.5*(128^3*sum(x^2) + 128^2*sum(s0^2+s1^2)), s0/s1 =
    // plain/alternating z-sums (kz=0 / kz=Nyquist planes = 2D FFTs of those).
    // decay loss (spectrum[9:]==0) = mean_{k=9..31}((k^{-5/3}/(9^{-5/3}+1e-8))^2),
    // data-independent. cascade = spectrum[1]/31.
    const double p = -5.0 / 3.0;
    const double denom = pow(9.0, p) + 1e-8;
    double acc = 0.0;
    for (int k = 9; k < 32; k++) {
        double en = pow((double)k, p) / denom;
        acc += en * en;
    }
    const double decay_loss = acc / 23.0;

    const double inv_npts = 1.0 / (128.0 * 128.0 * 65.0 * 4.0);
    const double c_casc   = 0.001 / 31.0;
    const double c0 = 0.01 * decay_loss;
    const double c1 = c_casc * 0.5 * 2097152.0 * inv_npts;   // * E = sum(x^2)
    const double c2 = c_casc * 0.5 * 16384.0   * inv_npts;   // * S = sum(s0^2+s1^2)

    spectral_kernel<<<NBLOCKS, 256>>>(x4, out, c0, c1, c2);
}

// round 8
// speedup vs baseline: 1.7273x; 1.0133x over previous
#include <cuda_runtime.h>
#include <math.h>
#include <stdint.h>

// ---- problem constants (shapes fixed by the dataset) ----
#define NROWS      196608LL   // 4*3*128*128 z-rows of 128 floats
#define TILE_ROWS  16         // rows per pipeline stage (8 KB)
#define STAGES     4
#define TILES_PB   16         // tiles per block -> 256 rows per block
#define NBLOCKS    768        // NROWS / (TILE_ROWS * TILES_PB)
#define TILE_F4    (TILE_ROWS * 32)      // 512 float4 per tile
#define TILE_BYTES (TILE_ROWS * 512)     // 8192

// Per-block partials: .x = sum(x^2), .y = sum over rows of (s0^2 + s1^2)
__device__ double2 g_part[NBLOCKS];
__device__ unsigned int g_ticket;   // zero-init; last block resets -> graph-replay safe

__device__ __forceinline__ uint32_t smem_u32(const void* p) {
    uint32_t a;
    asm("{ .reg .u64 t; cvta.to.shared.u64 t, %1; cvt.u32.u64 %0, t; }" : "=r"(a) : "l"(p));
    return a;
}
__device__ __forceinline__ void mbar_init(uint32_t mbar, uint32_t count) {
    asm volatile("mbarrier.init.shared.b64 [%0], %1;" :: "r"(mbar), "r"(count) : "memory");
}
__device__ __forceinline__ void mbar_expect_tx(uint32_t mbar, uint32_t bytes) {
    asm volatile("mbarrier.arrive.expect_tx.shared.b64 _, [%0], %1;" :: "r"(mbar), "r"(bytes) : "memory");
}
__device__ __forceinline__ void bulk_copy_g2s(uint32_t dst, const void* src, uint32_t bytes, uint32_t mbar) {
    asm volatile("cp.async.bulk.shared::cta.global.mbarrier::complete_tx::bytes [%0], [%1], %2, [%3];"
                 :: "r"(dst), "l"(src), "r"(bytes), "r"(mbar) : "memory");
}
__device__ __forceinline__ void mbar_wait_parity(uint32_t mbar, uint32_t parity) {
    asm volatile(
        "{\n\t"
        ".reg .pred P1;\n\t"
        "WAIT_LOOP_%=:\n\t"
        "mbarrier.try_wait.parity.shared.b64 P1, [%0], %1, 0x989680;\n\t"
        "@P1 bra.uni WAIT_DONE_%=;\n\t"
        "bra.uni WAIT_LOOP_%=;\n\t"
        "WAIT_DONE_%=:\n\t"
        "}"
        :: "r"(mbar), "r"(parity) : "memory");
}

// 4-deep cp.async.bulk pipeline: one elected thread keeps up to 3 8KB tile
// copies in flight (UBLKCP path, bypasses per-thread LDG) while 256 threads
// compute the oldest tile from smem.
//
// Compute: thread (r = tid>>4 in 0..15, o = tid&15) owns row r's 8 floats
// [o*8, o*8+8) as 2 LDS.128 with rotation j_eff = (j + ((o>>2)&1)) so every
// 8-lane LDS phase hits 8 distinct 4-bank groups (conflict-free).
// z of a float4 starts even -> alternating signs always +,-,+,-.
// Row combine over 16 o-lanes (5 shuffles): exchange across xor 8 (one per
// partial), then lo o-lanes reduce s0 while hi o-lanes reduce s1 through
// xor 4,2,1; lanes o==0 and o==8 accumulate t*t (warp total = s0^2+s1^2/row).
//
// Final loss = c0 + c1*E + c2*S (host-precomputed; see kernel_launch).
__global__ void __launch_bounds__(256) spectral_kernel(const float4* __restrict__ x4,
                                                       float* __restrict__ out,
                                                       double c0, double c1, double c2) {
    __shared__ alignas(1024) float4 buf[STAGES][TILE_F4];   // 4 x 8 KB
    __shared__ alignas(8) uint64_t mbar_store[STAGES];

    const int tid  = threadIdx.x;
    const int lane = tid & 31, wib = tid >> 5;
    uint32_t mb[STAGES];
    #pragma unroll
    for (int s = 0; s < STAGES; s++) mb[s] = smem_u32(&mbar_store[s]);

    const float4* __restrict__ src = x4 + (long long)blockIdx.x * (TILES_PB * TILE_F4);

    if (tid == 0) {
        #pragma unroll
        for (int s = 0; s < STAGES; s++) mbar_init(mb[s], 1);
        asm volatile("fence.proxy.async.shared::cta;" ::: "memory");
    }
    __syncthreads();

    if (tid == 0) {
        #pragma unroll
        for (int s = 0; s < STAGES; s++) {
            mbar_expect_tx(mb[s], TILE_BYTES);
            bulk_copy_g2s(smem_u32(&buf[s][0]), src + s * TILE_F4, TILE_BYTES, mb[s]);
        }
    }

    const int r   = tid >> 4;         // row within tile, 0..15
    const int o   = tid & 15;         // eighth-of-row, 0..7 -> but 16 chunks of 8 floats
    const int rot = (o >> 2) & 1;     // LDS phase rotation
    const bool lo = (o < 8);

    float e = 0.0f, ss = 0.0f;

    #pragma unroll
    for (int t = 0; t < TILES_PB; t++) {
        const int s = t & (STAGES - 1);
        mbar_wait_parity(mb[s], (t >> 2) & 1);

        const float4* __restrict__ my = &buf[s][r * 32 + o * 2];
        float p0 = 0.0f, p1 = 0.0f;
        #pragma unroll
        for (int j = 0; j < 2; j++) {
            const float4 w = my[j ^ rot];
            e  += w.x * w.x + w.y * w.y + w.z * w.z + w.w * w.w;
            p0 += (w.x + w.y) + (w.z + w.w);
            p1 += (w.x - w.y) + (w.z - w.w);
        }
        // combine the 16 o-lanes of this row: split tree
        const float a = __shfl_xor_sync(0xffffffffu, p0, 8);
        const float b = __shfl_xor_sync(0xffffffffu, p1, 8);
        float tv = lo ? (p0 + a) : (p1 + b);
        tv += __shfl_xor_sync(0xffffffffu, tv, 4);
        tv += __shfl_xor_sync(0xffffffffu, tv, 2);
        tv += __shfl_xor_sync(0xffffffffu, tv, 1);
        if ((o & 7) == 0) ss += tv * tv;     // o==0 holds s0, o==8 holds s1

        __syncthreads();                     // stage s fully consumed
        if (tid == 0 && t + STAGES < TILES_PB) {
            mbar_expect_tx(mb[s], TILE_BYTES);
            bulk_copy_g2s(smem_u32(&buf[s][0]),
                          src + (long long)(t + STAGES) * TILE_F4, TILE_BYTES, mb[s]);
        }
    }

    // warp-wide reduce of e and ss
    #pragma unroll
    for (int off = 16; off > 0; off >>= 1) {
        e  += __shfl_xor_sync(0xffffffffu, e,  off);
        ss += __shfl_xor_sync(0xffffffffu, ss, off);
    }

    __shared__ float sh_e[8];
    __shared__ float sh_s[8];
    if (lane == 0) { sh_e[wib] = e; sh_s[wib] = ss; }
    __syncthreads();

    __shared__ bool is_last;
    if (tid == 0) {
        double te = 0.0, ts = 0.0;
        #pragma unroll
        for (int i = 0; i < 8; i++) { te += (double)sh_e[i]; ts += (double)sh_s[i]; }
        g_part[blockIdx.x] = make_double2(te, ts);
        __threadfence();
        unsigned int tk = atomicAdd(&g_ticket, 1u);
        is_last = (tk == NBLOCKS - 1);
    }
    __syncthreads();

    if (!is_last) return;

    // ---- last block: reduce all partials (hot in L2) and finalize ----
    double te = 0.0, ts = 0.0;
    #pragma unroll
    for (int i = 0; i < NBLOCKS / 256; i++) {
        const double2 p = g_part[tid + i * 256];
        te += p.x; ts += p.y;
    }
    #pragma unroll
    for (int off = 16; off > 0; off >>= 1) {
        te += __shfl_xor_sync(0xffffffffu, te, off);
        ts += __shfl_xor_sync(0xffffffffu, ts, off);
    }
    __shared__ double fh_e[8];
    __shared__ double fh_s[8];
    if (lane == 0) { fh_e[wib] = te; fh_s[wib] = ts; }
    __syncthreads();

    if (tid == 0) {
        double E = 0.0, S = 0.0;
        #pragma unroll
        for (int i = 0; i < 8; i++) { E += fh_e[i]; S += fh_s[i]; }
        out[0] = (float)(c0 + c1 * E + c2 * S);
        g_ticket = 0;   // reset for next graph replay
    }
}

extern "C" void kernel_launch(void* const* d_in, const int* in_sizes, int n_in,
                              void* d_out, int out_size) {
    const float4* x4 = (const float4*)d_in[0];
    float* out = (float*)d_out;

    // ---- host-side constant folding ----
    // k_mag uses NORMALIZED fft freqs (<= sqrt(3)/2); k_bins = linspace(0,32,32)
    // (k_max = min(128,128,65)//2 = 32) has spacing 32/31 > sqrt(3)/2 => every
    // point lands in bin 1: spectrum[1] = E_half/(128*128*65*4), rest zero.
    // E_half via Parseval: 0.5*(128^3*sum(x^2) + 128^2*sum(s0^2+s1^2)), s0/s1 =
    // plain/alternating z-sums (kz=0 / kz=Nyquist planes = 2D FFTs of those).
    // decay loss (spectrum[9:]==0) = mean_{k=9..31}((k^{-5/3}/(9^{-5/3}+1e-8))^2),
    // data-independent. cascade = spectrum[1]/31.
    const double p = -5.0 / 3.0;
    const double denom = pow(9.0, p) + 1e-8;
    double acc = 0.0;
    for (int k = 9; k < 32; k++) {
        double en = pow((double)k, p) / denom;
        acc += en * en;
    }
    const double decay_loss = acc / 23.0;

    const double inv_npts = 1.0 / (128.0 * 128.0 * 65.0 * 4.0);
    const double c_casc   = 0.001 / 31.0;
    const double c0 = 0.01 * decay_loss;
    const double c1 = c_casc * 0.5 * 2097152.0 * inv_npts;   // * E = sum(x^2)
    const double c2 = c_casc * 0.5 * 16384.0   * inv_npts;   // * S = sum(s0^2+s1^2)

    spectral_kernel<<<NBLOCKS, 256>>>(x4, out, c0, c1, c2);
}